// round 10
// baseline (speedup 1.0000x reference)
#include <cuda_runtime.h>
#include <cuda_fp16.h>
#include <math.h>
#include <stdint.h>

// Problem constants
#define BATCH 4096
#define KIN   1024
#define HDIM  2048
#define OUTN  2

// ---------------- fp16 cp.async + ldmatrix GEMM config -----------------------
#define BM 128
#define BN 128
#define FBK 32                 // halves per K stage
#define LSTR 40                // smem row stride in halves (80B, 16B-aligned, conflict-free)
#define STAGES 4
#define STG_ELEMS (BM * LSTR)                    // 5120 halves per operand stage
#define SMEM_ZH (3 * STAGES * STG_ELEMS * 2)     // A + Bz + Bh = 122880 B
#define SMEM_R  (2 * STAGES * STG_ELEMS * 2)     // A + Br      =  81920 B
#define NIT (KIN / FBK)        // 32

// ---------------- tf32 mma.sync GEMM config (k_gemm_h; dead when h==0) -------
#define TBKH 16
#define TSPAD (TBKH + 1)

// -------- scratch (static device globals; no allocations allowed) ------------
__device__ float  g_az[HDIM];
__device__ float  g_ar[HDIM];
__device__ int    g_hflag;
__device__ float  g_zt  [(size_t)BATCH * HDIM];  // zt  (hflag==1)  OR  h_new (hflag==0)
__device__ float  g_u   [(size_t)BATCH * HDIM];
__device__ float  g_tpre[(size_t)BATCH * HDIM];
__device__ __half g_x16 [(size_t)BATCH * KIN];
__device__ __half g_wz16[(size_t)HDIM * KIN];
__device__ __half g_wr16[(size_t)HDIM * KIN];
__device__ __half g_wh16[(size_t)HDIM * KIN];

// -------- helpers --------
__device__ __forceinline__ unsigned f2tf32(float x) {
    unsigned r;
    asm("cvt.rna.tf32.f32 %0, %1;" : "=r"(r) : "f"(x));
    return r;
}

__device__ __forceinline__ float sigmoidf(float x) {
    return 1.0f / (1.0f + expf(-x));
}

__device__ __forceinline__ void mma_f16_k16(float* c, const unsigned* a, const unsigned* b) {
    asm("mma.sync.aligned.m16n8k16.row.col.f32.f16.f16.f32 "
        "{%0,%1,%2,%3}, {%4,%5,%6,%7}, {%8,%9}, {%0,%1,%2,%3};\n"
        : "+f"(c[0]), "+f"(c[1]), "+f"(c[2]), "+f"(c[3])
        : "r"(a[0]), "r"(a[1]), "r"(a[2]), "r"(a[3]),
          "r"(b[0]), "r"(b[1]));
}

__device__ __forceinline__ void mma_tf32(float* c, const unsigned* a, const unsigned* b) {
    asm("mma.sync.aligned.m16n8k8.row.col.f32.tf32.tf32.f32 "
        "{%0,%1,%2,%3}, {%4,%5,%6,%7}, {%8,%9}, {%0,%1,%2,%3};\n"
        : "+f"(c[0]), "+f"(c[1]), "+f"(c[2]), "+f"(c[3])
        : "r"(a[0]), "r"(a[1]), "r"(a[2]), "r"(a[3]),
          "r"(b[0]), "r"(b[1]));
}

__device__ __forceinline__ void sts_tf32_8(float* dst, float4 a, float4 b) {
    dst[0] = __uint_as_float(f2tf32(a.x));
    dst[1] = __uint_as_float(f2tf32(a.y));
    dst[2] = __uint_as_float(f2tf32(a.z));
    dst[3] = __uint_as_float(f2tf32(a.w));
    dst[4] = __uint_as_float(f2tf32(b.x));
    dst[5] = __uint_as_float(f2tf32(b.y));
    dst[6] = __uint_as_float(f2tf32(b.z));
    dst[7] = __uint_as_float(f2tf32(b.w));
}

__device__ __forceinline__ void cp_async16(uint32_t dst, const void* src) {
    asm volatile("cp.async.ca.shared.global [%0], [%1], 16;" :: "r"(dst), "l"(src) : "memory");
}
__device__ __forceinline__ void cp_commit() {
    asm volatile("cp.async.commit_group;" ::: "memory");
}
template <int N>
__device__ __forceinline__ void cp_wait() {
    asm volatile("cp.async.wait_group %0;" :: "n"(N) : "memory");
}

__device__ __forceinline__ void ldsm_x4(uint32_t* r, uint32_t addr) {
    asm volatile("ldmatrix.sync.aligned.m8n8.x4.shared.b16 {%0,%1,%2,%3}, [%4];"
                 : "=r"(r[0]), "=r"(r[1]), "=r"(r[2]), "=r"(r[3]) : "r"(addr));
}

// -------- k_flag --------
__global__ __launch_bounds__(256) void k_flag(const float* __restrict__ h) {
    int local = 0;
    for (int j = threadIdx.x; j < HDIM; j += blockDim.x)
        local |= (h[j] != 0.0f);
    int any = __syncthreads_or(local);
    if (threadIdx.x == 0) g_hflag = any;
}

// -------- k_cvt: fp32 -> fp16 (rn) --------
__global__ __launch_bounds__(256) void k_cvt(const float* __restrict__ src,
                                             __half* __restrict__ dst,
                                             int n4, int only_if_flag) {
    if (only_if_flag && g_hflag == 0) return;
    int idx = blockIdx.x * blockDim.x + threadIdx.x;
    const int stride = gridDim.x * blockDim.x;
    for (; idx < n4; idx += stride) {
        const float4 v = ((const float4*)src)[idx];
        __half2* d = (__half2*)dst + (size_t)idx * 2;
        d[0] = __floats2half2_rn(v.x, v.y);
        d[1] = __floats2half2_rn(v.z, v.w);
    }
}

// -------- k_gemv --------
__global__ __launch_bounds__(256) void k_gemv(
    const float* __restrict__ h,
    const float* __restrict__ Whz,
    const float* __restrict__ Whr,
    const float* __restrict__ bxz,
    const float* __restrict__ bxr)
{
    const int j = blockIdx.x;
    const int tid = threadIdx.x;
    if (g_hflag == 0) {
        if (tid == 0) { g_az[j] = bxz[j]; g_ar[j] = bxr[j]; }
        return;
    }
    const float* wz = Whz + (size_t)j * HDIM;
    const float* wr = Whr + (size_t)j * HDIM;
    float sz = 0.f, sr = 0.f;
    for (int k = tid; k < HDIM; k += 256) {
        const float hv = h[k];
        sz = fmaf(wz[k], hv, sz);
        sr = fmaf(wr[k], hv, sr);
    }
    __shared__ float rz[256], rr[256];
    rz[tid] = sz; rr[tid] = sr;
    __syncthreads();
    for (int off = 128; off > 0; off >>= 1) {
        if (tid < off) { rz[tid] += rz[tid + off]; rr[tid] += rr[tid + off]; }
        __syncthreads();
    }
    if (tid == 0) {
        g_az[j] = bxz[j] + rz[0];
        g_ar[j] = bxr[j] + rr[0];
    }
}

// ============ k_gemm_zh: fused z+h gate GEMM (shared A operand) ==============
// One CTA computes BOTH acc_z = x@Wz^T and acc_h = x@Wh^T for tile (m0,n0).
// hflag==0: writes h_new = (1-sigmoid(vz))*tanh(vh) into g_zt (single buffer).
// hflag==1: writes zt and tpre separately (k_gemm_h then accumulates).
__global__ __launch_bounds__(256, 1) void k_gemm_zh(
    const float* __restrict__ bxh)
{
    extern __shared__ __half sh[];
    const int m0 = blockIdx.x * BM;
    const int n0 = blockIdx.y * BN;
    const int hflag = g_hflag;

    const __half* Amat = g_x16;
    const __half* Bz   = g_wz16;
    const __half* Bh   = g_wh16;

    const int tid  = threadIdx.x;
    const int lane = tid & 31;
    const int wid  = tid >> 5;
    const int wm   = wid & 1;
    const int wn   = wid >> 1;
    const int g    = lane >> 2;
    const int t4   = lane & 3;

    const uint32_t smem_base = (uint32_t)__cvta_generic_to_shared(sh);
    const uint32_t regA  = 0;
    const uint32_t regBz = STAGES * STG_ELEMS;
    const uint32_t regBh = 2 * STAGES * STG_ELEMS;

    const int r0c = tid >> 2, c0c = (tid & 3) * 8;
    const int r1c = (tid + 256) >> 2, c1c = (tid & 3) * 8;

    const int a_row = ((lane >> 3) & 1) * 8 + (lane & 7);
    const int a_k   = ((lane >> 4) & 1) * 8;
    const int b_col = ((lane >> 4) & 1) * 8 + (lane & 7);
    const int b_k   = ((lane >> 3) & 1) * 8;

    float accz[4][4][4] = {};
    float acch[4][4][4] = {};

    auto issue = [&](int kblk, int buf) {
        const int kof = kblk * FBK;
        const uint32_t ab  = smem_base + (uint32_t)((regA  + buf * STG_ELEMS)) * 2;
        const uint32_t bzb = smem_base + (uint32_t)((regBz + buf * STG_ELEMS)) * 2;
        const uint32_t bhb = smem_base + (uint32_t)((regBh + buf * STG_ELEMS)) * 2;
        cp_async16(ab  + (uint32_t)(r0c * LSTR + c0c) * 2, Amat + (size_t)(m0 + r0c) * KIN + kof + c0c);
        cp_async16(ab  + (uint32_t)(r1c * LSTR + c1c) * 2, Amat + (size_t)(m0 + r1c) * KIN + kof + c1c);
        cp_async16(bzb + (uint32_t)(r0c * LSTR + c0c) * 2, Bz   + (size_t)(n0 + r0c) * KIN + kof + c0c);
        cp_async16(bzb + (uint32_t)(r1c * LSTR + c1c) * 2, Bz   + (size_t)(n0 + r1c) * KIN + kof + c1c);
        cp_async16(bhb + (uint32_t)(r0c * LSTR + c0c) * 2, Bh   + (size_t)(n0 + r0c) * KIN + kof + c0c);
        cp_async16(bhb + (uint32_t)(r1c * LSTR + c1c) * 2, Bh   + (size_t)(n0 + r1c) * KIN + kof + c1c);
    };

#pragma unroll
    for (int s = 0; s < STAGES - 1; s++) { issue(s, s); cp_commit(); }

    for (int it = 0; it < NIT; it++) {
        cp_wait<STAGES - 2>();
        __syncthreads();
        {
            const int ldk = it + STAGES - 1;
            if (ldk < NIT) issue(ldk, ldk & (STAGES - 1));
            cp_commit();
        }
        const int buf = it & (STAGES - 1);
        const uint32_t ab  = smem_base + (uint32_t)((regA  + buf * STG_ELEMS)) * 2;
        const uint32_t bzb = smem_base + (uint32_t)((regBz + buf * STG_ELEMS)) * 2;
        const uint32_t bhb = smem_base + (uint32_t)((regBh + buf * STG_ELEMS)) * 2;

#pragma unroll
        for (int ks = 0; ks < FBK; ks += 16) {
            uint32_t af[4][4], bfz[4][2], bfh[4][2];
#pragma unroll
            for (int mi = 0; mi < 4; mi++) {
                const int row = wm * 64 + mi * 16 + a_row;
                ldsm_x4(af[mi], ab + (uint32_t)(row * LSTR + ks + a_k) * 2);
            }
#pragma unroll
            for (int p = 0; p < 2; p++) {
                const int col = wn * 32 + p * 16 + b_col;
                uint32_t r4[4];
                ldsm_x4(r4, bzb + (uint32_t)(col * LSTR + ks + b_k) * 2);
                bfz[2 * p][0] = r4[0]; bfz[2 * p][1] = r4[1];
                bfz[2 * p + 1][0] = r4[2]; bfz[2 * p + 1][1] = r4[3];
                ldsm_x4(r4, bhb + (uint32_t)(col * LSTR + ks + b_k) * 2);
                bfh[2 * p][0] = r4[0]; bfh[2 * p][1] = r4[1];
                bfh[2 * p + 1][0] = r4[2]; bfh[2 * p + 1][1] = r4[3];
            }
#pragma unroll
            for (int mi = 0; mi < 4; mi++)
#pragma unroll
                for (int ni = 0; ni < 4; ni++) {
                    mma_f16_k16(accz[mi][ni], af[mi], bfz[ni]);
                    mma_f16_k16(acch[mi][ni], af[mi], bfh[ni]);
                }
        }
    }

    // ---- fused epilogue ----
#pragma unroll
    for (int mi = 0; mi < 4; mi++) {
#pragma unroll
        for (int ni = 0; ni < 4; ni++) {
            const int col   = n0 + wn * 32 + ni * 8 + t4 * 2;
            const int rbase = m0 + wm * 64 + mi * 16 + g;
            const float* cz = accz[mi][ni];
            const float* ch = acch[mi][ni];
#pragma unroll
            for (int half = 0; half < 2; half++) {
                const int row = rbase + half * 8;
                const size_t idx = (size_t)row * HDIM + col;
                const float vz0 = cz[half * 2 + 0] + g_az[col];
                const float vz1 = cz[half * 2 + 1] + g_az[col + 1];
                const float vh0 = ch[half * 2 + 0] + bxh[col];
                const float vh1 = ch[half * 2 + 1] + bxh[col + 1];
                if (hflag) {
                    float2 oz = { sigmoidf(vz0), sigmoidf(vz1) };
                    float2 oh = { vh0, vh1 };
                    *(float2*)(g_zt + idx)   = oz;
                    *(float2*)(g_tpre + idx) = oh;
                } else {
                    // h == 0: h_new = (1 - sigmoid(vz)) * tanh(vh), fully local
                    float2 hn = { (1.f - sigmoidf(vz0)) * tanhf(vh0),
                                  (1.f - sigmoidf(vz1)) * tanhf(vh1) };
                    *(float2*)(g_zt + idx) = hn;
                }
            }
        }
    }
}

// ============ k_gemm_r: r-gate GEMM (dead when h==0) =========================
__global__ __launch_bounds__(256, 2) void k_gemm_r(const float* __restrict__ hvec)
{
    extern __shared__ __half sh[];
    if (g_hflag == 0) return;

    const __half* Amat = g_x16;
    const __half* Bmat = g_wr16;
    const int m0 = blockIdx.x * BM;
    const int n0 = blockIdx.y * BN;

    const int tid  = threadIdx.x;
    const int lane = tid & 31;
    const int wid  = tid >> 5;
    const int wm   = wid & 1;
    const int wn   = wid >> 1;
    const int g    = lane >> 2;
    const int t4   = lane & 3;

    const uint32_t smem_base = (uint32_t)__cvta_generic_to_shared(sh);
    const uint32_t b_region  = STAGES * STG_ELEMS;

    const int r0c = tid >> 2, c0c = (tid & 3) * 8;
    const int r1c = (tid + 256) >> 2, c1c = (tid & 3) * 8;

    const int a_row = ((lane >> 3) & 1) * 8 + (lane & 7);
    const int a_k   = ((lane >> 4) & 1) * 8;
    const int b_col = ((lane >> 4) & 1) * 8 + (lane & 7);
    const int b_k   = ((lane >> 3) & 1) * 8;

    float acc[4][4][4] = {};

    auto issue = [&](int kblk, int buf) {
        const int kof = kblk * FBK;
        const uint32_t ab = smem_base + (uint32_t)(buf * STG_ELEMS) * 2;
        const uint32_t bb = smem_base + (uint32_t)(b_region + buf * STG_ELEMS) * 2;
        cp_async16(ab + (uint32_t)(r0c * LSTR + c0c) * 2, Amat + (size_t)(m0 + r0c) * KIN + kof + c0c);
        cp_async16(ab + (uint32_t)(r1c * LSTR + c1c) * 2, Amat + (size_t)(m0 + r1c) * KIN + kof + c1c);
        cp_async16(bb + (uint32_t)(r0c * LSTR + c0c) * 2, Bmat + (size_t)(n0 + r0c) * KIN + kof + c0c);
        cp_async16(bb + (uint32_t)(r1c * LSTR + c1c) * 2, Bmat + (size_t)(n0 + r1c) * KIN + kof + c1c);
    };

#pragma unroll
    for (int s = 0; s < STAGES - 1; s++) { issue(s, s); cp_commit(); }

    for (int it = 0; it < NIT; it++) {
        cp_wait<STAGES - 2>();
        __syncthreads();
        {
            const int ldk = it + STAGES - 1;
            if (ldk < NIT) issue(ldk, ldk & (STAGES - 1));
            cp_commit();
        }
        const int buf = it & (STAGES - 1);
        const uint32_t ab = smem_base + (uint32_t)(buf * STG_ELEMS) * 2;
        const uint32_t bb = smem_base + (uint32_t)(b_region + buf * STG_ELEMS) * 2;

#pragma unroll
        for (int ks = 0; ks < FBK; ks += 16) {
            uint32_t af[4][4], bf[4][2];
#pragma unroll
            for (int mi = 0; mi < 4; mi++) {
                const int row = wm * 64 + mi * 16 + a_row;
                ldsm_x4(af[mi], ab + (uint32_t)(row * LSTR + ks + a_k) * 2);
            }
#pragma unroll
            for (int p = 0; p < 2; p++) {
                const int col = wn * 32 + p * 16 + b_col;
                uint32_t r4[4];
                ldsm_x4(r4, bb + (uint32_t)(col * LSTR + ks + b_k) * 2);
                bf[2 * p][0] = r4[0]; bf[2 * p][1] = r4[1];
                bf[2 * p + 1][0] = r4[2]; bf[2 * p + 1][1] = r4[3];
            }
#pragma unroll
            for (int mi = 0; mi < 4; mi++)
#pragma unroll
                for (int ni = 0; ni < 4; ni++)
                    mma_f16_k16(acc[mi][ni], af[mi], bf[ni]);
        }
    }

#pragma unroll
    for (int mi = 0; mi < 4; mi++) {
#pragma unroll
        for (int ni = 0; ni < 4; ni++) {
            const int col   = n0 + wn * 32 + ni * 8 + t4 * 2;
            const int rbase = m0 + wm * 64 + mi * 16 + g;
            const float* c = acc[mi][ni];
#pragma unroll
            for (int half = 0; half < 2; half++) {
                const int row = rbase + half * 8;
                const size_t idx = (size_t)row * HDIM + col;
                float2 o = { sigmoidf(c[half * 2 + 0] + g_ar[col])     * hvec[col],
                             sigmoidf(c[half * 2 + 1] + g_ar[col + 1]) * hvec[col + 1] };
                *(float2*)(g_u + idx) = o;
            }
        }
    }
}

// ============ tf32 GEMM mainloop (k_gemm_h path; dead when h==0) =============
__device__ __forceinline__ void gemm_tf32_tile(
    const float* __restrict__ A, const float* __restrict__ Bm,
    int m0, int n0, int KD, float acc[4][4][4])
{
    __shared__ float As[2][BM][TSPAD];
    __shared__ float Bs[2][BN][TSPAD];

    const int tid  = threadIdx.x;
    const int r    = tid >> 1;
    const int cb   = (tid & 1) * 8;
    const int lane = tid & 31;
    const int wid  = tid >> 5;
    const int wm   = wid & 1;
    const int wn   = wid >> 1;
    const int g    = lane >> 2;
    const int t4   = lane & 3;

    const float* ag = A  + (size_t)(m0 + r) * KD + cb;
    const float* bg = Bm + (size_t)(n0 + r) * KD + cb;

    float4 av0 = *(const float4*)(ag);
    float4 av1 = *(const float4*)(ag + 4);
    float4 bv0 = *(const float4*)(bg);
    float4 bv1 = *(const float4*)(bg + 4);
    sts_tf32_8(&As[0][r][cb], av0, av1);
    sts_tf32_8(&Bs[0][r][cb], bv0, bv1);
    __syncthreads();

    int buf = 0;
    for (int k0 = 0; k0 < KD; k0 += TBKH) {
        const bool more = (k0 + TBKH) < KD;
        if (more) {
            av0 = *(const float4*)(ag + k0 + TBKH);
            av1 = *(const float4*)(ag + k0 + TBKH + 4);
            bv0 = *(const float4*)(bg + k0 + TBKH);
            bv1 = *(const float4*)(bg + k0 + TBKH + 4);
        }
#pragma unroll
        for (int kk = 0; kk < TBKH; kk += 8) {
            unsigned afr[4][4], bfr[4][2];
#pragma unroll
            for (int mi = 0; mi < 4; mi++) {
                const int row = wm * 64 + mi * 16 + g;
                afr[mi][0] = __float_as_uint(As[buf][row    ][kk + t4]);
                afr[mi][1] = __float_as_uint(As[buf][row + 8][kk + t4]);
                afr[mi][2] = __float_as_uint(As[buf][row    ][kk + 4 + t4]);
                afr[mi][3] = __float_as_uint(As[buf][row + 8][kk + 4 + t4]);
            }
#pragma unroll
            for (int ni = 0; ni < 4; ni++) {
                const int col = wn * 32 + ni * 8 + g;
                bfr[ni][0] = __float_as_uint(Bs[buf][col][kk + t4]);
                bfr[ni][1] = __float_as_uint(Bs[buf][col][kk + 4 + t4]);
            }
#pragma unroll
            for (int mi = 0; mi < 4; mi++)
#pragma unroll
                for (int ni = 0; ni < 4; ni++)
                    mma_tf32(acc[mi][ni], afr[mi], bfr[ni]);
        }
        if (more) {
            sts_tf32_8(&As[buf ^ 1][r][cb], av0, av1);
            sts_tf32_8(&Bs[buf ^ 1][r][cb], bv0, bv1);
        }
        __syncthreads();
        buf ^= 1;
    }
}

// -------- k_gemm_h: g_tpre += u @ Wh_h^T (only when h != 0) --------
__global__ __launch_bounds__(256) void k_gemm_h(const float* __restrict__ Whh) {
    if (g_hflag == 0) return;
    const int m0 = blockIdx.x * BM;
    const int n0 = blockIdx.y * BN;

    float acc[4][4][4] = {};
    gemm_tf32_tile(g_u, Whh, m0, n0, HDIM, acc);

    const int lane = threadIdx.x & 31;
    const int wid  = threadIdx.x >> 5;
    const int wm   = wid & 1;
    const int wn   = wid >> 1;
    const int g    = lane >> 2;
    const int t4   = lane & 3;

#pragma unroll
    for (int mi = 0; mi < 4; mi++) {
#pragma unroll
        for (int ni = 0; ni < 4; ni++) {
            const int col   = n0 + wn * 32 + ni * 8 + t4 * 2;
            const int rbase = m0 + wm * 64 + mi * 16 + g;
            const float* c = acc[mi][ni];
#pragma unroll
            for (int half = 0; half < 2; half++) {
                const int row = rbase + half * 8;
                float* p = g_tpre + (size_t)row * HDIM + col;
                float2 o = *(float2*)p;
                o.x += c[half * 2 + 0];
                o.y += c[half * 2 + 1];
                *(float2*)p = o;
            }
        }
    }
}

// -------- k_final: output head (h_new already computed when hflag==0) --------
__global__ __launch_bounds__(256) void k_final(
    const float* __restrict__ h,
    const float* __restrict__ Wy,
    const float* __restrict__ by,
    float* __restrict__ out)
{
    const int tid = threadIdx.x;
    const int hflag = g_hflag;
    const float* wy0 = Wy;
    const float* wy1 = Wy + HDIM;
    __shared__ float s0[256], s1[256];

#pragma unroll
    for (int sub = 0; sub < 2; sub++) {
        const int b = blockIdx.x * 2 + sub;
        float a0 = 0.f, a1 = 0.f;
        for (int j = tid; j < HDIM; j += 256) {
            const size_t idx = (size_t)b * HDIM + j;
            float hn;
            if (hflag) {
                const float z = g_zt[idx];
                hn = z * h[j] + (1.f - z) * tanhf(g_tpre[idx]);
            } else {
                hn = g_zt[idx];   // h_new precomputed by fused epilogue
            }
            a0 = fmaf(hn, wy0[j], a0);
            a1 = fmaf(hn, wy1[j], a1);
        }
        s0[tid] = a0; s1[tid] = a1;
        __syncthreads();
        for (int off = 128; off > 0; off >>= 1) {
            if (tid < off) { s0[tid] += s0[tid + off]; s1[tid] += s1[tid + off]; }
            __syncthreads();
        }
        if (tid == 0) {
            out[b * OUTN + 0] = s0[0] + by[0];
            out[b * OUTN + 1] = s1[0] + by[1];
        }
        __syncthreads();
    }
}

// -------- launch --------
extern "C" void kernel_launch(void* const* d_in, const int* in_sizes, int n_in,
                              void* d_out, int out_size) {
    const float* x   = (const float*)d_in[0];
    const float* h   = (const float*)d_in[1];
    const float* Wxz = (const float*)d_in[2];
    const float* bxz = (const float*)d_in[3];
    const float* Wxr = (const float*)d_in[4];
    const float* bxr = (const float*)d_in[5];
    const float* Wxh = (const float*)d_in[6];
    const float* bxh = (const float*)d_in[7];
    const float* Whz = (const float*)d_in[8];
    const float* Whr = (const float*)d_in[9];
    const float* Whh = (const float*)d_in[10];
    const float* Wy  = (const float*)d_in[11];
    const float* by  = (const float*)d_in[12];
    float* out = (float*)d_out;

    static int smem_set = 0;
    if (!smem_set) {
        cudaFuncSetAttribute(k_gemm_zh, cudaFuncAttributeMaxDynamicSharedMemorySize, SMEM_ZH);
        cudaFuncSetAttribute(k_gemm_r,  cudaFuncAttributeMaxDynamicSharedMemorySize, SMEM_R);
        smem_set = 1;
    }

    k_flag<<<1, 256>>>(h);

    __half* x16p;  cudaGetSymbolAddress((void**)&x16p,  g_x16);
    __half* wz16p; cudaGetSymbolAddress((void**)&wz16p, g_wz16);
    __half* wr16p; cudaGetSymbolAddress((void**)&wr16p, g_wr16);
    __half* wh16p; cudaGetSymbolAddress((void**)&wh16p, g_wh16);
    k_cvt<<<2048, 256>>>(x,   x16p,  BATCH * KIN / 4, 0);
    k_cvt<<<1024, 256>>>(Wxz, wz16p, HDIM * KIN / 4, 0);
    k_cvt<<<1024, 256>>>(Wxr, wr16p, HDIM * KIN / 4, 1);
    k_cvt<<<1024, 256>>>(Wxh, wh16p, HDIM * KIN / 4, 0);

    k_gemv<<<HDIM, 256>>>(h, Whz, Whr, bxz, bxr);

    dim3 gz(BATCH / BM, HDIM / BN);
    k_gemm_zh<<<gz, 256, SMEM_ZH>>>(bxh);
    k_gemm_r<<<gz, 256, SMEM_R>>>(h);

    k_gemm_h<<<gz, 256>>>(Whh);

    k_final<<<BATCH / 2, 256>>>(h, Wy, by, out);
}

// round 11
// speedup vs baseline: 1.0718x; 1.0718x over previous
#include <cuda_runtime.h>
#include <cuda_fp16.h>
#include <math.h>
#include <stdint.h>

// Problem constants
#define BATCH 4096
#define KIN   1024
#define HDIM  2048
#define OUTN  2

// ---------------- fp16 cp.async + ldmatrix GEMM config -----------------------
#define BM 128
#define BN 128
#define FBK 32                 // halves per K stage
#define LSTR 40                // smem row stride in halves (80B, 16B-aligned, conflict-free)
#define STAGES 4
#define STG_ELEMS (BM * LSTR)                    // 5120 halves per operand stage
#define SMEM_ZH (3 * STAGES * STG_ELEMS * 2)     // A + Bz + Bh = 122880 B
#define SMEM_R  (2 * STAGES * STG_ELEMS * 2)     // A + Br      =  81920 B
#define NIT (KIN / FBK)        // 32

// ---------------- tf32 mma.sync GEMM config (k_gemm_h; dead when h==0) -------
#define TBKH 16
#define TSPAD (TBKH + 1)

// -------- scratch (static device globals; no allocations allowed) ------------
__device__ float  g_az[HDIM];
__device__ float  g_ar[HDIM];
__device__ int    g_hflag;
__device__ float  g_zt  [(size_t)BATCH * HDIM];  // zt (hflag==1) OR h_new (hflag==0)
__device__ float  g_u   [(size_t)BATCH * HDIM];
__device__ float  g_tpre[(size_t)BATCH * HDIM];
__device__ __half g_x16 [(size_t)BATCH * KIN];
__device__ __half g_wz16[(size_t)HDIM * KIN];
__device__ __half g_wr16[(size_t)HDIM * KIN];
__device__ __half g_wh16[(size_t)HDIM * KIN];

// -------- helpers --------
__device__ __forceinline__ unsigned f2tf32(float x) {
    unsigned r;
    asm("cvt.rna.tf32.f32 %0, %1;" : "=r"(r) : "f"(x));
    return r;
}

__device__ __forceinline__ float sigmoidf(float x) {
    return 1.0f / (1.0f + expf(-x));
}

__device__ __forceinline__ void mma_f16_k16(float* c, const unsigned* a, const unsigned* b) {
    asm("mma.sync.aligned.m16n8k16.row.col.f32.f16.f16.f32 "
        "{%0,%1,%2,%3}, {%4,%5,%6,%7}, {%8,%9}, {%0,%1,%2,%3};\n"
        : "+f"(c[0]), "+f"(c[1]), "+f"(c[2]), "+f"(c[3])
        : "r"(a[0]), "r"(a[1]), "r"(a[2]), "r"(a[3]),
          "r"(b[0]), "r"(b[1]));
}

__device__ __forceinline__ void mma_tf32(float* c, const unsigned* a, const unsigned* b) {
    asm("mma.sync.aligned.m16n8k8.row.col.f32.tf32.tf32.f32 "
        "{%0,%1,%2,%3}, {%4,%5,%6,%7}, {%8,%9}, {%0,%1,%2,%3};\n"
        : "+f"(c[0]), "+f"(c[1]), "+f"(c[2]), "+f"(c[3])
        : "r"(a[0]), "r"(a[1]), "r"(a[2]), "r"(a[3]),
          "r"(b[0]), "r"(b[1]));
}

__device__ __forceinline__ void sts_tf32_8(float* dst, float4 a, float4 b) {
    dst[0] = __uint_as_float(f2tf32(a.x));
    dst[1] = __uint_as_float(f2tf32(a.y));
    dst[2] = __uint_as_float(f2tf32(a.z));
    dst[3] = __uint_as_float(f2tf32(a.w));
    dst[4] = __uint_as_float(f2tf32(b.x));
    dst[5] = __uint_as_float(f2tf32(b.y));
    dst[6] = __uint_as_float(f2tf32(b.z));
    dst[7] = __uint_as_float(f2tf32(b.w));
}

__device__ __forceinline__ void cp_async16(uint32_t dst, const void* src) {
    asm volatile("cp.async.ca.shared.global [%0], [%1], 16;" :: "r"(dst), "l"(src) : "memory");
}
__device__ __forceinline__ void cp_commit() {
    asm volatile("cp.async.commit_group;" ::: "memory");
}
template <int N>
__device__ __forceinline__ void cp_wait() {
    asm volatile("cp.async.wait_group %0;" :: "n"(N) : "memory");
}

__device__ __forceinline__ void ldsm_x4(uint32_t* r, uint32_t addr) {
    asm volatile("ldmatrix.sync.aligned.m8n8.x4.shared.b16 {%0,%1,%2,%3}, [%4];"
                 : "=r"(r[0]), "=r"(r[1]), "=r"(r[2]), "=r"(r[3]) : "r"(addr));
}

// -------- k_flag --------
__global__ __launch_bounds__(256) void k_flag(const float* __restrict__ h) {
    int local = 0;
    for (int j = threadIdx.x; j < HDIM; j += blockDim.x)
        local |= (h[j] != 0.0f);
    int any = __syncthreads_or(local);
    if (threadIdx.x == 0) g_hflag = any;
}

// -------- k_cvt: fp32 -> fp16 (rn) --------
__global__ __launch_bounds__(256) void k_cvt(const float* __restrict__ src,
                                             __half* __restrict__ dst,
                                             int n4, int only_if_flag) {
    if (only_if_flag && g_hflag == 0) return;
    int idx = blockIdx.x * blockDim.x + threadIdx.x;
    const int stride = gridDim.x * blockDim.x;
    for (; idx < n4; idx += stride) {
        const float4 v = ((const float4*)src)[idx];
        __half2* d = (__half2*)dst + (size_t)idx * 2;
        d[0] = __floats2half2_rn(v.x, v.y);
        d[1] = __floats2half2_rn(v.z, v.w);
    }
}

// -------- k_gemv --------
__global__ __launch_bounds__(256) void k_gemv(
    const float* __restrict__ h,
    const float* __restrict__ Whz,
    const float* __restrict__ Whr,
    const float* __restrict__ bxz,
    const float* __restrict__ bxr)
{
    const int j = blockIdx.x;
    const int tid = threadIdx.x;
    if (g_hflag == 0) {
        if (tid == 0) { g_az[j] = bxz[j]; g_ar[j] = bxr[j]; }
        return;
    }
    const float* wz = Whz + (size_t)j * HDIM;
    const float* wr = Whr + (size_t)j * HDIM;
    float sz = 0.f, sr = 0.f;
    for (int k = tid; k < HDIM; k += 256) {
        const float hv = h[k];
        sz = fmaf(wz[k], hv, sz);
        sr = fmaf(wr[k], hv, sr);
    }
    __shared__ float rz[256], rr[256];
    rz[tid] = sz; rr[tid] = sr;
    __syncthreads();
    for (int off = 128; off > 0; off >>= 1) {
        if (tid < off) { rz[tid] += rz[tid + off]; rr[tid] += rr[tid + off]; }
        __syncthreads();
    }
    if (tid == 0) {
        g_az[j] = bxz[j] + rz[0];
        g_ar[j] = bxr[j] + rr[0];
    }
}

// ============ k_gemm_zh: fused z+h GEMM, 512 threads (16 warps, 4x4 grid) ====
// Warp tile 32x32 per gate -> 64 acc floats/thread, regs ~110 (<128 cap).
// hflag==0: h_new = (1-sigmoid(vz))*tanh(vh) written to g_zt only.
// hflag==1: zt and tpre written separately (k_gemm_h accumulates later).
__global__ __launch_bounds__(512, 1) void k_gemm_zh(
    const float* __restrict__ bxh)
{
    extern __shared__ __half sh[];
    const int m0 = blockIdx.x * BM;
    const int n0 = blockIdx.y * BN;
    const int hflag = g_hflag;

    const __half* Amat = g_x16;
    const __half* Bz   = g_wz16;
    const __half* Bh   = g_wh16;

    const int tid  = threadIdx.x;
    const int lane = tid & 31;
    const int wid  = tid >> 5;          // 0..15
    const int wm   = wid & 3;           // warp row group (32 rows each)
    const int wn   = wid >> 2;          // warp col group (32 cols each)
    const int g    = lane >> 2;
    const int t4   = lane & 3;

    const uint32_t smem_base = (uint32_t)__cvta_generic_to_shared(sh);
    const uint32_t regA  = 0;
    const uint32_t regBz = STAGES * STG_ELEMS;
    const uint32_t regBh = 2 * STAGES * STG_ELEMS;

    // loader: exactly one 16B chunk per thread per operand (512 chunks/stage)
    const int rc = tid >> 2;            // row 0..127
    const int cc = (tid & 3) * 8;       // halves offset 0/8/16/24

    const int a_row = ((lane >> 3) & 1) * 8 + (lane & 7);
    const int a_k   = ((lane >> 4) & 1) * 8;
    const int b_col = ((lane >> 4) & 1) * 8 + (lane & 7);
    const int b_k   = ((lane >> 3) & 1) * 8;

    float accz[2][4][4] = {};
    float acch[2][4][4] = {};

    auto issue = [&](int kblk, int buf) {
        const int kof = kblk * FBK;
        const uint32_t ab  = smem_base + (uint32_t)((regA  + buf * STG_ELEMS)) * 2;
        const uint32_t bzb = smem_base + (uint32_t)((regBz + buf * STG_ELEMS)) * 2;
        const uint32_t bhb = smem_base + (uint32_t)((regBh + buf * STG_ELEMS)) * 2;
        const uint32_t so = (uint32_t)(rc * LSTR + cc) * 2;
        cp_async16(ab  + so, Amat + (size_t)(m0 + rc) * KIN + kof + cc);
        cp_async16(bzb + so, Bz   + (size_t)(n0 + rc) * KIN + kof + cc);
        cp_async16(bhb + so, Bh   + (size_t)(n0 + rc) * KIN + kof + cc);
    };

#pragma unroll
    for (int s = 0; s < STAGES - 1; s++) { issue(s, s); cp_commit(); }

    for (int it = 0; it < NIT; it++) {
        cp_wait<STAGES - 2>();
        __syncthreads();
        {
            const int ldk = it + STAGES - 1;
            if (ldk < NIT) issue(ldk, ldk & (STAGES - 1));
            cp_commit();
        }
        const int buf = it & (STAGES - 1);
        const uint32_t ab  = smem_base + (uint32_t)((regA  + buf * STG_ELEMS)) * 2;
        const uint32_t bzb = smem_base + (uint32_t)((regBz + buf * STG_ELEMS)) * 2;
        const uint32_t bhb = smem_base + (uint32_t)((regBh + buf * STG_ELEMS)) * 2;

#pragma unroll
        for (int ks = 0; ks < FBK; ks += 16) {
            uint32_t af[2][4], bfz[4][2], bfh[4][2];
#pragma unroll
            for (int mi = 0; mi < 2; mi++) {
                const int row = wm * 32 + mi * 16 + a_row;
                ldsm_x4(af[mi], ab + (uint32_t)(row * LSTR + ks + a_k) * 2);
            }
#pragma unroll
            for (int p = 0; p < 2; p++) {
                const int col = wn * 32 + p * 16 + b_col;
                uint32_t r4[4];
                ldsm_x4(r4, bzb + (uint32_t)(col * LSTR + ks + b_k) * 2);
                bfz[2 * p][0] = r4[0]; bfz[2 * p][1] = r4[1];
                bfz[2 * p + 1][0] = r4[2]; bfz[2 * p + 1][1] = r4[3];
                ldsm_x4(r4, bhb + (uint32_t)(col * LSTR + ks + b_k) * 2);
                bfh[2 * p][0] = r4[0]; bfh[2 * p][1] = r4[1];
                bfh[2 * p + 1][0] = r4[2]; bfh[2 * p + 1][1] = r4[3];
            }
#pragma unroll
            for (int mi = 0; mi < 2; mi++)
#pragma unroll
                for (int ni = 0; ni < 4; ni++) {
                    mma_f16_k16(accz[mi][ni], af[mi], bfz[ni]);
                    mma_f16_k16(acch[mi][ni], af[mi], bfh[ni]);
                }
        }
    }

    // ---- fused epilogue ----
#pragma unroll
    for (int mi = 0; mi < 2; mi++) {
#pragma unroll
        for (int ni = 0; ni < 4; ni++) {
            const int col   = n0 + wn * 32 + ni * 8 + t4 * 2;
            const int rbase = m0 + wm * 32 + mi * 16 + g;
            const float* cz = accz[mi][ni];
            const float* ch = acch[mi][ni];
#pragma unroll
            for (int half = 0; half < 2; half++) {
                const int row = rbase + half * 8;
                const size_t idx = (size_t)row * HDIM + col;
                const float vz0 = cz[half * 2 + 0] + g_az[col];
                const float vz1 = cz[half * 2 + 1] + g_az[col + 1];
                const float vh0 = ch[half * 2 + 0] + bxh[col];
                const float vh1 = ch[half * 2 + 1] + bxh[col + 1];
                if (hflag) {
                    float2 oz = { sigmoidf(vz0), sigmoidf(vz1) };
                    float2 oh = { vh0, vh1 };
                    *(float2*)(g_zt + idx)   = oz;
                    *(float2*)(g_tpre + idx) = oh;
                } else {
                    float2 hn = { (1.f - sigmoidf(vz0)) * tanhf(vh0),
                                  (1.f - sigmoidf(vz1)) * tanhf(vh1) };
                    *(float2*)(g_zt + idx) = hn;
                }
            }
        }
    }
}

// ============ k_gemm_r: r-gate GEMM (dead when h==0), R9-proven 256t =========
__global__ __launch_bounds__(256, 2) void k_gemm_r(const float* __restrict__ hvec)
{
    extern __shared__ __half sh[];
    if (g_hflag == 0) return;

    const __half* Amat = g_x16;
    const __half* Bmat = g_wr16;
    const int m0 = blockIdx.x * BM;
    const int n0 = blockIdx.y * BN;

    const int tid  = threadIdx.x;
    const int lane = tid & 31;
    const int wid  = tid >> 5;
    const int wm   = wid & 1;
    const int wn   = wid >> 1;
    const int g    = lane >> 2;
    const int t4   = lane & 3;

    const uint32_t smem_base = (uint32_t)__cvta_generic_to_shared(sh);
    const uint32_t b_region  = STAGES * STG_ELEMS;

    const int r0c = tid >> 2, c0c = (tid & 3) * 8;
    const int r1c = (tid + 256) >> 2, c1c = (tid & 3) * 8;

    const int a_row = ((lane >> 3) & 1) * 8 + (lane & 7);
    const int a_k   = ((lane >> 4) & 1) * 8;
    const int b_col = ((lane >> 4) & 1) * 8 + (lane & 7);
    const int b_k   = ((lane >> 3) & 1) * 8;

    float acc[4][4][4] = {};

    auto issue = [&](int kblk, int buf) {
        const int kof = kblk * FBK;
        const uint32_t ab = smem_base + (uint32_t)(buf * STG_ELEMS) * 2;
        const uint32_t bb = smem_base + (uint32_t)(b_region + buf * STG_ELEMS) * 2;
        cp_async16(ab + (uint32_t)(r0c * LSTR + c0c) * 2, Amat + (size_t)(m0 + r0c) * KIN + kof + c0c);
        cp_async16(ab + (uint32_t)(r1c * LSTR + c1c) * 2, Amat + (size_t)(m0 + r1c) * KIN + kof + c1c);
        cp_async16(bb + (uint32_t)(r0c * LSTR + c0c) * 2, Bmat + (size_t)(n0 + r0c) * KIN + kof + c0c);
        cp_async16(bb + (uint32_t)(r1c * LSTR + c1c) * 2, Bmat + (size_t)(n0 + r1c) * KIN + kof + c1c);
    };

#pragma unroll
    for (int s = 0; s < STAGES - 1; s++) { issue(s, s); cp_commit(); }

    for (int it = 0; it < NIT; it++) {
        cp_wait<STAGES - 2>();
        __syncthreads();
        {
            const int ldk = it + STAGES - 1;
            if (ldk < NIT) issue(ldk, ldk & (STAGES - 1));
            cp_commit();
        }
        const int buf = it & (STAGES - 1);
        const uint32_t ab = smem_base + (uint32_t)(buf * STG_ELEMS) * 2;
        const uint32_t bb = smem_base + (uint32_t)(b_region + buf * STG_ELEMS) * 2;

#pragma unroll
        for (int ks = 0; ks < FBK; ks += 16) {
            uint32_t af[4][4], bf[4][2];
#pragma unroll
            for (int mi = 0; mi < 4; mi++) {
                const int row = wm * 64 + mi * 16 + a_row;
                ldsm_x4(af[mi], ab + (uint32_t)(row * LSTR + ks + a_k) * 2);
            }
#pragma unroll
            for (int p = 0; p < 2; p++) {
                const int col = wn * 32 + p * 16 + b_col;
                uint32_t r4[4];
                ldsm_x4(r4, bb + (uint32_t)(col * LSTR + ks + b_k) * 2);
                bf[2 * p][0] = r4[0]; bf[2 * p][1] = r4[1];
                bf[2 * p + 1][0] = r4[2]; bf[2 * p + 1][1] = r4[3];
            }
#pragma unroll
            for (int mi = 0; mi < 4; mi++)
#pragma unroll
                for (int ni = 0; ni < 4; ni++)
                    mma_f16_k16(acc[mi][ni], af[mi], bf[ni]);
        }
    }

#pragma unroll
    for (int mi = 0; mi < 4; mi++) {
#pragma unroll
        for (int ni = 0; ni < 4; ni++) {
            const int col   = n0 + wn * 32 + ni * 8 + t4 * 2;
            const int rbase = m0 + wm * 64 + mi * 16 + g;
            const float* c = acc[mi][ni];
#pragma unroll
            for (int half = 0; half < 2; half++) {
                const int row = rbase + half * 8;
                const size_t idx = (size_t)row * HDIM + col;
                float2 o = { sigmoidf(c[half * 2 + 0] + g_ar[col])     * hvec[col],
                             sigmoidf(c[half * 2 + 1] + g_ar[col + 1]) * hvec[col + 1] };
                *(float2*)(g_u + idx) = o;
            }
        }
    }
}

// ============ tf32 GEMM mainloop (k_gemm_h path; dead when h==0) =============
__device__ __forceinline__ void gemm_tf32_tile(
    const float* __restrict__ A, const float* __restrict__ Bm,
    int m0, int n0, int KD, float acc[4][4][4])
{
    __shared__ float As[2][BM][TSPAD];
    __shared__ float Bs[2][BN][TSPAD];

    const int tid  = threadIdx.x;
    const int r    = tid >> 1;
    const int cb   = (tid & 1) * 8;
    const int lane = tid & 31;
    const int wid  = tid >> 5;
    const int wm   = wid & 1;
    const int wn   = wid >> 1;
    const int g    = lane >> 2;
    const int t4   = lane & 3;

    const float* ag = A  + (size_t)(m0 + r) * KD + cb;
    const float* bg = Bm + (size_t)(n0 + r) * KD + cb;

    float4 av0 = *(const float4*)(ag);
    float4 av1 = *(const float4*)(ag + 4);
    float4 bv0 = *(const float4*)(bg);
    float4 bv1 = *(const float4*)(bg + 4);
    sts_tf32_8(&As[0][r][cb], av0, av1);
    sts_tf32_8(&Bs[0][r][cb], bv0, bv1);
    __syncthreads();

    int buf = 0;
    for (int k0 = 0; k0 < KD; k0 += TBKH) {
        const bool more = (k0 + TBKH) < KD;
        if (more) {
            av0 = *(const float4*)(ag + k0 + TBKH);
            av1 = *(const float4*)(ag + k0 + TBKH + 4);
            bv0 = *(const float4*)(bg + k0 + TBKH);
            bv1 = *(const float4*)(bg + k0 + TBKH + 4);
        }
#pragma unroll
        for (int kk = 0; kk < TBKH; kk += 8) {
            unsigned afr[4][4], bfr[4][2];
#pragma unroll
            for (int mi = 0; mi < 4; mi++) {
                const int row = wm * 64 + mi * 16 + g;
                afr[mi][0] = __float_as_uint(As[buf][row    ][kk + t4]);
                afr[mi][1] = __float_as_uint(As[buf][row + 8][kk + t4]);
                afr[mi][2] = __float_as_uint(As[buf][row    ][kk + 4 + t4]);
                afr[mi][3] = __float_as_uint(As[buf][row + 8][kk + 4 + t4]);
            }
#pragma unroll
            for (int ni = 0; ni < 4; ni++) {
                const int col = wn * 32 + ni * 8 + g;
                bfr[ni][0] = __float_as_uint(Bs[buf][col][kk + t4]);
                bfr[ni][1] = __float_as_uint(Bs[buf][col][kk + 4 + t4]);
            }
#pragma unroll
            for (int mi = 0; mi < 4; mi++)
#pragma unroll
                for (int ni = 0; ni < 4; ni++)
                    mma_tf32(acc[mi][ni], afr[mi], bfr[ni]);
        }
        if (more) {
            sts_tf32_8(&As[buf ^ 1][r][cb], av0, av1);
            sts_tf32_8(&Bs[buf ^ 1][r][cb], bv0, bv1);
        }
        __syncthreads();
        buf ^= 1;
    }
}

// -------- k_gemm_h: g_tpre += u @ Wh_h^T (only when h != 0) --------
__global__ __launch_bounds__(256) void k_gemm_h(const float* __restrict__ Whh) {
    if (g_hflag == 0) return;
    const int m0 = blockIdx.x * BM;
    const int n0 = blockIdx.y * BN;

    float acc[4][4][4] = {};
    gemm_tf32_tile(g_u, Whh, m0, n0, HDIM, acc);

    const int lane = threadIdx.x & 31;
    const int wid  = threadIdx.x >> 5;
    const int wm   = wid & 1;
    const int wn   = wid >> 1;
    const int g    = lane >> 2;
    const int t4   = lane & 3;

#pragma unroll
    for (int mi = 0; mi < 4; mi++) {
#pragma unroll
        for (int ni = 0; ni < 4; ni++) {
            const int col   = n0 + wn * 32 + ni * 8 + t4 * 2;
            const int rbase = m0 + wm * 64 + mi * 16 + g;
            const float* c = acc[mi][ni];
#pragma unroll
            for (int half = 0; half < 2; half++) {
                const int row = rbase + half * 8;
                float* p = g_tpre + (size_t)row * HDIM + col;
                float2 o = *(float2*)p;
                o.x += c[half * 2 + 0];
                o.y += c[half * 2 + 1];
                *(float2*)p = o;
            }
        }
    }
}

// -------- k_final: output head (h_new precomputed when hflag==0) --------
__global__ __launch_bounds__(256) void k_final(
    const float* __restrict__ h,
    const float* __restrict__ Wy,
    const float* __restrict__ by,
    float* __restrict__ out)
{
    const int tid = threadIdx.x;
    const int hflag = g_hflag;
    const float* wy0 = Wy;
    const float* wy1 = Wy + HDIM;
    __shared__ float s0[256], s1[256];

#pragma unroll
    for (int sub = 0; sub < 2; sub++) {
        const int b = blockIdx.x * 2 + sub;
        float a0 = 0.f, a1 = 0.f;
        for (int j = tid; j < HDIM; j += 256) {
            const size_t idx = (size_t)b * HDIM + j;
            float hn;
            if (hflag) {
                const float z = g_zt[idx];
                hn = z * h[j] + (1.f - z) * tanhf(g_tpre[idx]);
            } else {
                hn = g_zt[idx];
            }
            a0 = fmaf(hn, wy0[j], a0);
            a1 = fmaf(hn, wy1[j], a1);
        }
        s0[tid] = a0; s1[tid] = a1;
        __syncthreads();
        for (int off = 128; off > 0; off >>= 1) {
            if (tid < off) { s0[tid] += s0[tid + off]; s1[tid] += s1[tid + off]; }
            __syncthreads();
        }
        if (tid == 0) {
            out[b * OUTN + 0] = s0[0] + by[0];
            out[b * OUTN + 1] = s1[0] + by[1];
        }
        __syncthreads();
    }
}

// -------- launch --------
extern "C" void kernel_launch(void* const* d_in, const int* in_sizes, int n_in,
                              void* d_out, int out_size) {
    const float* x   = (const float*)d_in[0];
    const float* h   = (const float*)d_in[1];
    const float* Wxz = (const float*)d_in[2];
    const float* bxz = (const float*)d_in[3];
    const float* Wxr = (const float*)d_in[4];
    const float* bxr = (const float*)d_in[5];
    const float* Wxh = (const float*)d_in[6];
    const float* bxh = (const float*)d_in[7];
    const float* Whz = (const float*)d_in[8];
    const float* Whr = (const float*)d_in[9];
    const float* Whh = (const float*)d_in[10];
    const float* Wy  = (const float*)d_in[11];
    const float* by  = (const float*)d_in[12];
    float* out = (float*)d_out;

    static int smem_set = 0;
    if (!smem_set) {
        cudaFuncSetAttribute(k_gemm_zh, cudaFuncAttributeMaxDynamicSharedMemorySize, SMEM_ZH);
        cudaFuncSetAttribute(k_gemm_r,  cudaFuncAttributeMaxDynamicSharedMemorySize, SMEM_R);
        smem_set = 1;
    }

    k_flag<<<1, 256>>>(h);

    __half* x16p;  cudaGetSymbolAddress((void**)&x16p,  g_x16);
    __half* wz16p; cudaGetSymbolAddress((void**)&wz16p, g_wz16);
    __half* wr16p; cudaGetSymbolAddress((void**)&wr16p, g_wr16);
    __half* wh16p; cudaGetSymbolAddress((void**)&wh16p, g_wh16);
    k_cvt<<<2048, 256>>>(x,   x16p,  BATCH * KIN / 4, 0);
    k_cvt<<<1024, 256>>>(Wxz, wz16p, HDIM * KIN / 4, 0);
    k_cvt<<<1024, 256>>>(Wxr, wr16p, HDIM * KIN / 4, 1);
    k_cvt<<<1024, 256>>>(Wxh, wh16p, HDIM * KIN / 4, 0);

    k_gemv<<<HDIM, 256>>>(h, Whz, Whr, bxz, bxr);

    dim3 gz(BATCH / BM, HDIM / BN);
    k_gemm_zh<<<gz, 512, SMEM_ZH>>>(bxh);
    k_gemm_r<<<gz, 256, SMEM_R>>>(h);

    k_gemm_h<<<gz, 256>>>(Whh);

    k_final<<<BATCH / 2, 256>>>(h, Wy, by, out);
}

// round 13
// speedup vs baseline: 1.1763x; 1.0974x over previous
#include <cuda_runtime.h>
#include <cuda_fp16.h>
#include <math.h>
#include <stdint.h>

// Problem constants
#define BATCH 4096
#define KIN   1024
#define HDIM  2048
#define OUTN  2

// ---------------- fp16 cp.async + ldmatrix GEMM config (live path) -----------
#define BM 128
#define BN 128
#define FBK 32                 // halves per K stage
#define LSTR 40                // smem row stride in halves (80B, 16B-aligned, conflict-free)
#define STAGES 4
#define STG_ELEMS (BM * LSTR)                 // halves per operand stage (5120)
#define SMEM_HALVES (2 * STAGES * STG_ELEMS)  // 40960 halves = 80 KB
#define NIT (KIN / FBK)        // 32

// ---------------- tf32 mma.sync GEMM config (k_gemm_h; dead when h==0) -------
#define TBKH 16
#define TSPAD (TBKH + 1)

// -------- scratch (static device globals; no allocations allowed) ------------
__device__ float  g_az[HDIM];
__device__ float  g_ar[HDIM];
__device__ int    g_hflag;
__device__ float  g_zt  [(size_t)BATCH * HDIM];   // fp32 zt   (hflag==1 path)
__device__ float  g_u   [(size_t)BATCH * HDIM];
__device__ float  g_tpre[(size_t)BATCH * HDIM];   // fp32 tpre (hflag==1 path)
__device__ __half g_omz16[(size_t)BATCH * HDIM];  // (1-zt)  fp16 (hflag==0 path)
__device__ __half g_th16 [(size_t)BATCH * HDIM];  // tanh(t) fp16 (hflag==0 path)
__device__ __half g_x16 [(size_t)BATCH * KIN];
__device__ __half g_wz16[(size_t)HDIM * KIN];
__device__ __half g_wr16[(size_t)HDIM * KIN];
__device__ __half g_wh16[(size_t)HDIM * KIN];

// -------- helpers --------
__device__ __forceinline__ unsigned f2tf32(float x) {
    unsigned r;
    asm("cvt.rna.tf32.f32 %0, %1;" : "=r"(r) : "f"(x));
    return r;
}

__device__ __forceinline__ float sigmoidf(float x) {
    return 1.0f / (1.0f + expf(-x));
}

__device__ __forceinline__ void mma_f16_k16(float* c, const unsigned* a, const unsigned* b) {
    asm("mma.sync.aligned.m16n8k16.row.col.f32.f16.f16.f32 "
        "{%0,%1,%2,%3}, {%4,%5,%6,%7}, {%8,%9}, {%0,%1,%2,%3};\n"
        : "+f"(c[0]), "+f"(c[1]), "+f"(c[2]), "+f"(c[3])
        : "r"(a[0]), "r"(a[1]), "r"(a[2]), "r"(a[3]),
          "r"(b[0]), "r"(b[1]));
}

__device__ __forceinline__ void mma_tf32(float* c, const unsigned* a, const unsigned* b) {
    asm("mma.sync.aligned.m16n8k8.row.col.f32.tf32.tf32.f32 "
        "{%0,%1,%2,%3}, {%4,%5,%6,%7}, {%8,%9}, {%0,%1,%2,%3};\n"
        : "+f"(c[0]), "+f"(c[1]), "+f"(c[2]), "+f"(c[3])
        : "r"(a[0]), "r"(a[1]), "r"(a[2]), "r"(a[3]),
          "r"(b[0]), "r"(b[1]));
}

__device__ __forceinline__ void sts_tf32_8(float* dst, float4 a, float4 b) {
    dst[0] = __uint_as_float(f2tf32(a.x));
    dst[1] = __uint_as_float(f2tf32(a.y));
    dst[2] = __uint_as_float(f2tf32(a.z));
    dst[3] = __uint_as_float(f2tf32(a.w));
    dst[4] = __uint_as_float(f2tf32(b.x));
    dst[5] = __uint_as_float(f2tf32(b.y));
    dst[6] = __uint_as_float(f2tf32(b.z));
    dst[7] = __uint_as_float(f2tf32(b.w));
}

__device__ __forceinline__ void cp_async16(uint32_t dst, const void* src) {
    asm volatile("cp.async.ca.shared.global [%0], [%1], 16;" :: "r"(dst), "l"(src) : "memory");
}
__device__ __forceinline__ void cp_commit() {
    asm volatile("cp.async.commit_group;" ::: "memory");
}
template <int N>
__device__ __forceinline__ void cp_wait() {
    asm volatile("cp.async.wait_group %0;" :: "n"(N) : "memory");
}

__device__ __forceinline__ void ldsm_x4(uint32_t* r, uint32_t addr) {
    asm volatile("ldmatrix.sync.aligned.m8n8.x4.shared.b16 {%0,%1,%2,%3}, [%4];"
                 : "=r"(r[0]), "=r"(r[1]), "=r"(r[2]), "=r"(r[3]) : "r"(addr));
}

// -------- k_flag --------
__global__ __launch_bounds__(256) void k_flag(const float* __restrict__ h) {
    int local = 0;
    for (int j = threadIdx.x; j < HDIM; j += blockDim.x)
        local |= (h[j] != 0.0f);
    int any = __syncthreads_or(local);
    if (threadIdx.x == 0) g_hflag = any;
}

// -------- k_cvt_all: fp32 -> fp16 of x, Wz, Wh (+Wr when h != 0), one launch -
__global__ __launch_bounds__(256) void k_cvt_all(
    const float* __restrict__ x,
    const float* __restrict__ Wxz,
    const float* __restrict__ Wxr,
    const float* __restrict__ Wxh)
{
    const int flag = g_hflag;
    const int XC = BATCH * KIN / 4;        // float4 chunks in x
    const int WC = HDIM * KIN / 4;         // float4 chunks per weight
    const int total = XC + 3 * WC;
    int idx = blockIdx.x * blockDim.x + threadIdx.x;
    const int stride = gridDim.x * blockDim.x;
    for (; idx < total; idx += stride) {
        const float* src; __half* dst; int off;
        if (idx < XC)               { src = x;   dst = g_x16;  off = idx; }
        else if (idx < XC + WC)     { src = Wxz; dst = g_wz16; off = idx - XC; }
        else if (idx < XC + 2 * WC) { src = Wxh; dst = g_wh16; off = idx - XC - WC; }
        else { if (!flag) continue;   src = Wxr; dst = g_wr16; off = idx - XC - 2 * WC; }
        const float4 v = ((const float4*)src)[off];
        __half2* d = (__half2*)dst + (size_t)off * 2;
        d[0] = __floats2half2_rn(v.x, v.y);
        d[1] = __floats2half2_rn(v.z, v.w);
    }
}

// -------- k_gemv --------
__global__ __launch_bounds__(256) void k_gemv(
    const float* __restrict__ h,
    const float* __restrict__ Whz,
    const float* __restrict__ Whr,
    const float* __restrict__ bxz,
    const float* __restrict__ bxr)
{
    const int j = blockIdx.x;
    const int tid = threadIdx.x;
    if (g_hflag == 0) {
        if (tid == 0) { g_az[j] = bxz[j]; g_ar[j] = bxr[j]; }
        return;
    }
    const float* wz = Whz + (size_t)j * HDIM;
    const float* wr = Whr + (size_t)j * HDIM;
    float sz = 0.f, sr = 0.f;
    for (int k = tid; k < HDIM; k += 256) {
        const float hv = h[k];
        sz = fmaf(wz[k], hv, sz);
        sr = fmaf(wr[k], hv, sr);
    }
    __shared__ float rz[256], rr[256];
    rz[tid] = sz; rr[tid] = sr;
    __syncthreads();
    for (int off = 128; off > 0; off >>= 1) {
        if (tid < off) { rz[tid] += rz[tid + off]; rr[tid] += rr[tid + off]; }
        __syncthreads();
    }
    if (tid == 0) {
        g_az[j] = bxz[j] + rz[0];
        g_ar[j] = bxr[j] + rr[0];
    }
}

// ============ k_gemm_in: fp16 cp.async 4-stage + ldmatrix + fused epilogue ===
// C(128x128) = x16[m0..,:] * W16[n0..,:]^T. 8 warps (2x4), warp tile 64x32.
// hflag==0: gate0 stores (1-sigmoid) fp16, gate2 stores tanh fp16 (small bufs).
// hflag==1: fp32 zt / tpre as before (general path).
__global__ __launch_bounds__(256, 2) void k_gemm_in(
    const float* __restrict__ bxh,
    const float* __restrict__ hvec)
{
    extern __shared__ __half sh[];
    const int tiles_per_gate = HDIM / BN;   // 16
    const int gate = blockIdx.y / tiles_per_gate;
    const int hflag = g_hflag;
    if (gate == 1 && hflag == 0) return;    // r-gate dead when h == 0

    const __half* Bmat = (gate == 0) ? g_wz16 : ((gate == 1) ? g_wr16 : g_wh16);
    const __half* Amat = g_x16;
    const int m0 = blockIdx.x * BM;
    const int n0 = (blockIdx.y % tiles_per_gate) * BN;

    const int tid  = threadIdx.x;
    const int lane = tid & 31;
    const int wid  = tid >> 5;
    const int wm   = wid & 1;
    const int wn   = wid >> 1;
    const int g    = lane >> 2;
    const int t4   = lane & 3;

    const uint32_t smem_base = (uint32_t)__cvta_generic_to_shared(sh);
    const uint32_t b_region  = STAGES * STG_ELEMS;

    const int r0c = tid >> 2, c0c = (tid & 3) * 8;
    const int r1c = (tid + 256) >> 2, c1c = (tid & 3) * 8;

    const int a_row = ((lane >> 3) & 1) * 8 + (lane & 7);
    const int a_k   = ((lane >> 4) & 1) * 8;
    const int b_col = ((lane >> 4) & 1) * 8 + (lane & 7);
    const int b_k   = ((lane >> 3) & 1) * 8;

    float acc[4][4][4] = {};

    auto issue = [&](int kblk, int buf) {
        const int kof = kblk * FBK;
        const uint32_t ab = smem_base + (uint32_t)(buf * STG_ELEMS) * 2;
        const uint32_t bb = smem_base + (uint32_t)(b_region + buf * STG_ELEMS) * 2;
        cp_async16(ab + (uint32_t)(r0c * LSTR + c0c) * 2, Amat + (size_t)(m0 + r0c) * KIN + kof + c0c);
        cp_async16(ab + (uint32_t)(r1c * LSTR + c1c) * 2, Amat + (size_t)(m0 + r1c) * KIN + kof + c1c);
        cp_async16(bb + (uint32_t)(r0c * LSTR + c0c) * 2, Bmat + (size_t)(n0 + r0c) * KIN + kof + c0c);
        cp_async16(bb + (uint32_t)(r1c * LSTR + c1c) * 2, Bmat + (size_t)(n0 + r1c) * KIN + kof + c1c);
    };

#pragma unroll
    for (int s = 0; s < STAGES - 1; s++) { issue(s, s); cp_commit(); }

    for (int it = 0; it < NIT; it++) {
        cp_wait<STAGES - 2>();
        __syncthreads();
        {
            const int ldk = it + STAGES - 1;
            if (ldk < NIT) issue(ldk, ldk & (STAGES - 1));
            cp_commit();
        }
        const int buf = it & (STAGES - 1);
        const uint32_t ab = smem_base + (uint32_t)(buf * STG_ELEMS) * 2;
        const uint32_t bb = smem_base + (uint32_t)(b_region + buf * STG_ELEMS) * 2;

#pragma unroll
        for (int ks = 0; ks < FBK; ks += 16) {
            uint32_t af[4][4], bf[4][2];
#pragma unroll
            for (int mi = 0; mi < 4; mi++) {
                const int row = wm * 64 + mi * 16 + a_row;
                ldsm_x4(af[mi], ab + (uint32_t)(row * LSTR + ks + a_k) * 2);
            }
#pragma unroll
            for (int p = 0; p < 2; p++) {
                const int col = wn * 32 + p * 16 + b_col;
                uint32_t r4[4];
                ldsm_x4(r4, bb + (uint32_t)(col * LSTR + ks + b_k) * 2);
                bf[2 * p][0] = r4[0]; bf[2 * p][1] = r4[1];
                bf[2 * p + 1][0] = r4[2]; bf[2 * p + 1][1] = r4[3];
            }
#pragma unroll
            for (int mi = 0; mi < 4; mi++)
#pragma unroll
                for (int ni = 0; ni < 4; ni++)
                    mma_f16_k16(acc[mi][ni], af[mi], bf[ni]);
        }
    }

    // ---- fused gate epilogue ----
#pragma unroll
    for (int mi = 0; mi < 4; mi++) {
#pragma unroll
        for (int ni = 0; ni < 4; ni++) {
            const int col   = n0 + wn * 32 + ni * 8 + t4 * 2;
            const int rbase = m0 + wm * 64 + mi * 16 + g;
            const float* c = acc[mi][ni];
#pragma unroll
            for (int half = 0; half < 2; half++) {
                const int row = rbase + half * 8;
                const float v0 = c[half * 2 + 0];
                const float v1 = c[half * 2 + 1];
                const size_t idx = (size_t)row * HDIM + col;
                if (gate == 0) {
                    const float s0 = sigmoidf(v0 + g_az[col]);
                    const float s1 = sigmoidf(v1 + g_az[col + 1]);
                    if (hflag) {
                        float2 o = { s0, s1 };
                        *(float2*)(g_zt + idx) = o;
                    } else {
                        *(__half2*)(g_omz16 + idx) = __floats2half2_rn(1.f - s0, 1.f - s1);
                    }
                } else if (gate == 1) {
                    float2 o = { sigmoidf(v0 + g_ar[col])     * hvec[col],
                                 sigmoidf(v1 + g_ar[col + 1]) * hvec[col + 1] };
                    *(float2*)(g_u + idx) = o;
                } else {
                    const float t0 = v0 + bxh[col];
                    const float t1 = v1 + bxh[col + 1];
                    if (hflag) {
                        float2 o = { t0, t1 };
                        *(float2*)(g_tpre + idx) = o;
                    } else {
                        *(__half2*)(g_th16 + idx) = __floats2half2_rn(tanhf(t0), tanhf(t1));
                    }
                }
            }
        }
    }
}

// ============ tf32 GEMM mainloop (k_gemm_h path; dead when h==0) =============
__device__ __forceinline__ void gemm_tf32_tile(
    const float* __restrict__ A, const float* __restrict__ Bm,
    int m0, int n0, int KD, float acc[4][4][4])
{
    __shared__ float As[2][BM][TSPAD];
    __shared__ float Bs[2][BN][TSPAD];

    const int tid  = threadIdx.x;
    const int r    = tid >> 1;
    const int cb   = (tid & 1) * 8;
    const int lane = tid & 31;
    const int wid  = tid >> 5;
    const int wm   = wid & 1;
    const int wn   = wid >> 1;
    const int g    = lane >> 2;
    const int t4   = lane & 3;

    const float* ag = A  + (size_t)(m0 + r) * KD + cb;
    const float* bg = Bm + (size_t)(n0 + r) * KD + cb;

    float4 av0 = *(const float4*)(ag);
    float4 av1 = *(const float4*)(ag + 4);
    float4 bv0 = *(const float4*)(bg);
    float4 bv1 = *(const float4*)(bg + 4);
    sts_tf32_8(&As[0][r][cb], av0, av1);
    sts_tf32_8(&Bs[0][r][cb], bv0, bv1);
    __syncthreads();

    int buf = 0;
    for (int k0 = 0; k0 < KD; k0 += TBKH) {
        const bool more = (k0 + TBKH) < KD;
        if (more) {
            av0 = *(const float4*)(ag + k0 + TBKH);
            av1 = *(const float4*)(ag + k0 + TBKH + 4);
            bv0 = *(const float4*)(bg + k0 + TBKH);
            bv1 = *(const float4*)(bg + k0 + TBKH + 4);
        }
#pragma unroll
        for (int kk = 0; kk < TBKH; kk += 8) {
            unsigned afr[4][4], bfr[4][2];
#pragma unroll
            for (int mi = 0; mi < 4; mi++) {
                const int row = wm * 64 + mi * 16 + g;
                afr[mi][0] = __float_as_uint(As[buf][row    ][kk + t4]);
                afr[mi][1] = __float_as_uint(As[buf][row + 8][kk + t4]);
                afr[mi][2] = __float_as_uint(As[buf][row    ][kk + 4 + t4]);
                afr[mi][3] = __float_as_uint(As[buf][row + 8][kk + 4 + t4]);
            }
#pragma unroll
            for (int ni = 0; ni < 4; ni++) {
                const int col = wn * 32 + ni * 8 + g;
                bfr[ni][0] = __float_as_uint(Bs[buf][col][kk + t4]);
                bfr[ni][1] = __float_as_uint(Bs[buf][col][kk + 4 + t4]);
            }
#pragma unroll
            for (int mi = 0; mi < 4; mi++)
#pragma unroll
                for (int ni = 0; ni < 4; ni++)
                    mma_tf32(acc[mi][ni], afr[mi], bfr[ni]);
        }
        if (more) {
            sts_tf32_8(&As[buf ^ 1][r][cb], av0, av1);
            sts_tf32_8(&Bs[buf ^ 1][r][cb], bv0, bv1);
        }
        __syncthreads();
        buf ^= 1;
    }
}

// -------- k_gemm_h: g_tpre += u @ Wh_h^T (only when h != 0) --------
__global__ __launch_bounds__(256) void k_gemm_h(const float* __restrict__ Whh) {
    if (g_hflag == 0) return;
    const int m0 = blockIdx.x * BM;
    const int n0 = blockIdx.y * BN;

    float acc[4][4][4] = {};
    gemm_tf32_tile(g_u, Whh, m0, n0, HDIM, acc);

    const int lane = threadIdx.x & 31;
    const int wid  = threadIdx.x >> 5;
    const int wm   = wid & 1;
    const int wn   = wid >> 1;
    const int g    = lane >> 2;
    const int t4   = lane & 3;

#pragma unroll
    for (int mi = 0; mi < 4; mi++) {
#pragma unroll
        for (int ni = 0; ni < 4; ni++) {
            const int col   = n0 + wn * 32 + ni * 8 + t4 * 2;
            const int rbase = m0 + wm * 64 + mi * 16 + g;
            const float* c = acc[mi][ni];
#pragma unroll
            for (int half = 0; half < 2; half++) {
                const int row = rbase + half * 8;
                float* p = g_tpre + (size_t)row * HDIM + col;
                float2 o = *(float2*)p;
                o.x += c[half * 2 + 0];
                o.y += c[half * 2 + 1];
                *(float2*)p = o;
            }
        }
    }
}

// -------- k_final: output head --------
// hflag==0: hn = (1-z)*tanh  from two fp16 streams (half traffic).
// hflag==1: hn = z*h + (1-z)*tanh(tpre)  from fp32 streams.
__global__ __launch_bounds__(256) void k_final(
    const float* __restrict__ h,
    const float* __restrict__ Wy,
    const float* __restrict__ by,
    float* __restrict__ out)
{
    const int tid = threadIdx.x;
    const int hflag = g_hflag;
    const float* wy0 = Wy;
    const float* wy1 = Wy + HDIM;
    __shared__ float s0[256], s1[256];

#pragma unroll
    for (int sub = 0; sub < 2; sub++) {
        const int b = blockIdx.x * 2 + sub;
        float a0 = 0.f, a1 = 0.f;
        if (hflag) {
            for (int j = tid; j < HDIM; j += 256) {
                const size_t idx = (size_t)b * HDIM + j;
                const float z = g_zt[idx];
                const float hn = z * h[j] + (1.f - z) * tanhf(g_tpre[idx]);
                a0 = fmaf(hn, wy0[j], a0);
                a1 = fmaf(hn, wy1[j], a1);
            }
        } else {
            const __half2* om = (const __half2*)(g_omz16 + (size_t)b * HDIM);
            const __half2* th = (const __half2*)(g_th16  + (size_t)b * HDIM);
            for (int j2 = tid; j2 < HDIM / 2; j2 += 256) {
                const float2 o = __half22float2(om[j2]);
                const float2 t = __half22float2(th[j2]);
                const float hn0 = o.x * t.x;
                const float hn1 = o.y * t.y;
                const int j = j2 * 2;
                a0 = fmaf(hn0, wy0[j], fmaf(hn1, wy0[j + 1], a0));
                a1 = fmaf(hn0, wy1[j], fmaf(hn1, wy1[j + 1], a1));
            }
        }
        s0[tid] = a0; s1[tid] = a1;
        __syncthreads();
        for (int off = 128; off > 0; off >>= 1) {
            if (tid < off) { s0[tid] += s0[tid + off]; s1[tid] += s1[tid + off]; }
            __syncthreads();
        }
        if (tid == 0) {
            out[b * OUTN + 0] = s0[0] + by[0];
            out[b * OUTN + 1] = s1[0] + by[1];
        }
        __syncthreads();
    }
}

// -------- launch --------
extern "C" void kernel_launch(void* const* d_in, const int* in_sizes, int n_in,
                              void* d_out, int out_size) {
    const float* x   = (const float*)d_in[0];
    const float* h   = (const float*)d_in[1];
    const float* Wxz = (const float*)d_in[2];
    const float* bxz = (const float*)d_in[3];
    const float* Wxr = (const float*)d_in[4];
    const float* bxr = (const float*)d_in[5];
    const float* Wxh = (const float*)d_in[6];
    const float* bxh = (const float*)d_in[7];
    const float* Whz = (const float*)d_in[8];
    const float* Whr = (const float*)d_in[9];
    const float* Whh = (const float*)d_in[10];
    const float* Wy  = (const float*)d_in[11];
    const float* by  = (const float*)d_in[12];
    float* out = (float*)d_out;

    static int smem_set = 0;
    if (!smem_set) {
        cudaFuncSetAttribute(k_gemm_in, cudaFuncAttributeMaxDynamicSharedMemorySize,
                             SMEM_HALVES * 2);
        smem_set = 1;
    }

    k_flag<<<1, 256>>>(h);
    k_cvt_all<<<2048, 256>>>(x, Wxz, Wxr, Wxh);
    k_gemv<<<HDIM, 256>>>(h, Whz, Whr, bxz, bxr);

    dim3 g1(BATCH / BM, 3 * (HDIM / BN));
    k_gemm_in<<<g1, 256, SMEM_HALVES * 2>>>(bxh, h);

    dim3 g2(BATCH / BM, HDIM / BN);
    k_gemm_h<<<g2, 256>>>(Whh);

    k_final<<<BATCH / 2, 256>>>(h, Wy, by, out);
}

// round 16
// speedup vs baseline: 1.2823x; 1.0902x over previous
#include <cuda_runtime.h>
#include <cuda_fp16.h>
#include <math.h>
#include <stdint.h>

// Problem constants (GRU classifier: B=4096, K=1024, H=2048, OUT=2)
#define BATCH 4096
#define KIN   1024
#define HDIM  2048
#define OUTN  2

// ------ fp16 cp.async 3-stage (64-k) + ldmatrix GEMM config (live path) ------
#define BM 128
#define BN 128
#define FBK 64                 // halves per K stage
#define LSTR 72                // row stride in halves: 144B, 16B-aligned, ldmatrix conflict-free
#define STAGES 3
#define STG_ELEMS (BM * LSTR)                    // 9216 halves per operand stage
#define SMEM_BYTES (2 * STAGES * STG_ELEMS * 2)  // 110592 B (x2 CTAs = 221184 <= 228KB)
#define NIT (KIN / FBK)        // 16 K-iterations

// ------ tf32 mma.sync GEMM config (k_gemm_h; dead when h == 0) ---------------
#define TBKH 16
#define TSPAD (TBKH + 1)

// ------ scratch (static device globals; no allocations allowed) --------------
__device__ float  g_az[HDIM];
__device__ float  g_ar[HDIM];
__device__ int    g_hflag;
__device__ float  g_zt  [(size_t)BATCH * HDIM];   // fp32 zt   (hflag==1)
__device__ float  g_u   [(size_t)BATCH * HDIM];
__device__ float  g_tpre[(size_t)BATCH * HDIM];   // fp32 tpre (hflag==1)
__device__ __half g_omz16[(size_t)BATCH * HDIM];  // (1-zt)  fp16 (hflag==0)
__device__ __half g_th16 [(size_t)BATCH * HDIM];  // tanh(t) fp16 (hflag==0)
__device__ __half g_x16 [(size_t)BATCH * KIN];
__device__ __half g_wz16[(size_t)HDIM * KIN];
__device__ __half g_wr16[(size_t)HDIM * KIN];
__device__ __half g_wh16[(size_t)HDIM * KIN];

// ------ helpers --------------------------------------------------------------
__device__ __forceinline__ unsigned f2tf32(float x) {
    unsigned r;
    asm("cvt.rna.tf32.f32 %0, %1;" : "=r"(r) : "f"(x));
    return r;
}

__device__ __forceinline__ float sigmoidf(float x) {
    return 1.0f / (1.0f + expf(-x));
}

__device__ __forceinline__ void mma_f16_k16(float* c, const unsigned* a, const unsigned* b) {
    asm("mma.sync.aligned.m16n8k16.row.col.f32.f16.f16.f32 "
        "{%0,%1,%2,%3}, {%4,%5,%6,%7}, {%8,%9}, {%0,%1,%2,%3};\n"
        : "+f"(c[0]), "+f"(c[1]), "+f"(c[2]), "+f"(c[3])
        : "r"(a[0]), "r"(a[1]), "r"(a[2]), "r"(a[3]),
          "r"(b[0]), "r"(b[1]));
}

__device__ __forceinline__ void mma_tf32(float* c, const unsigned* a, const unsigned* b) {
    asm("mma.sync.aligned.m16n8k8.row.col.f32.tf32.tf32.f32 "
        "{%0,%1,%2,%3}, {%4,%5,%6,%7}, {%8,%9}, {%0,%1,%2,%3};\n"
        : "+f"(c[0]), "+f"(c[1]), "+f"(c[2]), "+f"(c[3])
        : "r"(a[0]), "r"(a[1]), "r"(a[2]), "r"(a[3]),
          "r"(b[0]), "r"(b[1]));
}

__device__ __forceinline__ void sts_tf32_8(float* dst, float4 a, float4 b) {
    dst[0] = __uint_as_float(f2tf32(a.x));
    dst[1] = __uint_as_float(f2tf32(a.y));
    dst[2] = __uint_as_float(f2tf32(a.z));
    dst[3] = __uint_as_float(f2tf32(a.w));
    dst[4] = __uint_as_float(f2tf32(b.x));
    dst[5] = __uint_as_float(f2tf32(b.y));
    dst[6] = __uint_as_float(f2tf32(b.z));
    dst[7] = __uint_as_float(f2tf32(b.w));
}

__device__ __forceinline__ void cp_async16(uint32_t dst, const void* src) {
    asm volatile("cp.async.cg.shared.global [%0], [%1], 16;" :: "r"(dst), "l"(src) : "memory");
}
__device__ __forceinline__ void cp_commit() {
    asm volatile("cp.async.commit_group;" ::: "memory");
}
template <int N>
__device__ __forceinline__ void cp_wait() {
    asm volatile("cp.async.wait_group %0;" :: "n"(N) : "memory");
}

__device__ __forceinline__ void ldsm_x4(uint32_t* r, uint32_t addr) {
    asm volatile("ldmatrix.sync.aligned.m8n8.x4.shared.b16 {%0,%1,%2,%3}, [%4];"
                 : "=r"(r[0]), "=r"(r[1]), "=r"(r[2]), "=r"(r[3]) : "r"(addr));
}

// ------ k_flag: does h have any nonzero element? -----------------------------
__global__ __launch_bounds__(256) void k_flag(const float* __restrict__ h) {
    int local = 0;
    for (int j = threadIdx.x; j < HDIM; j += blockDim.x)
        local |= (h[j] != 0.0f);
    int any = __syncthreads_or(local);
    if (threadIdx.x == 0) g_hflag = any;
}

// ------ k_cvt_all: fp32 -> fp16 of x, Wz, Wh (+Wr when h != 0) ---------------
__global__ __launch_bounds__(256) void k_cvt_all(
    const float* __restrict__ x,
    const float* __restrict__ Wxz,
    const float* __restrict__ Wxr,
    const float* __restrict__ Wxh)
{
    const int flag = g_hflag;
    const int XC = BATCH * KIN / 4;
    const int WC = HDIM * KIN / 4;
    const int total = XC + 3 * WC;
    int idx = blockIdx.x * blockDim.x + threadIdx.x;
    const int stride = gridDim.x * blockDim.x;
    for (; idx < total; idx += stride) {
        const float* src; __half* dst; int off;
        if (idx < XC)               { src = x;   dst = g_x16;  off = idx; }
        else if (idx < XC + WC)     { src = Wxz; dst = g_wz16; off = idx - XC; }
        else if (idx < XC + 2 * WC) { src = Wxh; dst = g_wh16; off = idx - XC - WC; }
        else { if (!flag) continue;   src = Wxr; dst = g_wr16; off = idx - XC - 2 * WC; }
        const float4 v = ((const float4*)src)[off];
        __half2* d = (__half2*)dst + (size_t)off * 2;
        d[0] = __floats2half2_rn(v.x, v.y);
        d[1] = __floats2half2_rn(v.z, v.w);
    }
}

// ------ k_gemv: a_z = bx_z + Wh_z@h ; a_r = bx_r + Wh_r@h --------------------
__global__ __launch_bounds__(256) void k_gemv(
    const float* __restrict__ h,
    const float* __restrict__ Whz,
    const float* __restrict__ Whr,
    const float* __restrict__ bxz,
    const float* __restrict__ bxr)
{
    const int j = blockIdx.x;
    const int tid = threadIdx.x;
    if (g_hflag == 0) {
        if (tid == 0) { g_az[j] = bxz[j]; g_ar[j] = bxr[j]; }
        return;
    }
    const float* wz = Whz + (size_t)j * HDIM;
    const float* wr = Whr + (size_t)j * HDIM;
    float sz = 0.f, sr = 0.f;
    for (int k = tid; k < HDIM; k += 256) {
        const float hv = h[k];
        sz = fmaf(wz[k], hv, sz);
        sr = fmaf(wr[k], hv, sr);
    }
    __shared__ float rz[256], rr[256];
    rz[tid] = sz; rr[tid] = sr;
    __syncthreads();
    for (int off = 128; off > 0; off >>= 1) {
        if (tid < off) { rz[tid] += rz[tid + off]; rr[tid] += rr[tid + off]; }
        __syncthreads();
    }
    if (tid == 0) {
        g_az[j] = bxz[j] + rz[0];
        g_ar[j] = bxr[j] + rr[0];
    }
}

// ====== k_gemm_in: x16 @ W16^T, 3-stage 64-k pipeline, fused gate epilogue ===
__global__ __launch_bounds__(256, 2) void k_gemm_in(
    const float* __restrict__ bxh,
    const float* __restrict__ hvec)
{
    extern __shared__ __half sh[];
    const int tiles_per_gate = HDIM / BN;   // 16
    const int gate = blockIdx.y / tiles_per_gate;
    const int hflag = g_hflag;
    if (gate == 1 && hflag == 0) return;    // r-gate dead when h == 0

    const __half* Bmat = (gate == 0) ? g_wz16 : ((gate == 1) ? g_wr16 : g_wh16);
    const __half* Amat = g_x16;
    const int m0 = blockIdx.x * BM;
    const int n0 = (blockIdx.y % tiles_per_gate) * BN;

    const int tid  = threadIdx.x;
    const int lane = tid & 31;
    const int wid  = tid >> 5;
    const int wm   = wid & 1;
    const int wn   = wid >> 1;
    const int g    = lane >> 2;
    const int t4   = lane & 3;

    const uint32_t smem_base = (uint32_t)__cvta_generic_to_shared(sh);
    const uint32_t b_region  = STAGES * STG_ELEMS;

    // loader: per operand per stage, 1024 16B-chunks over 256 threads (x4)
    int rowv[4], colv[4];
#pragma unroll
    for (int p = 0; p < 4; p++) {
        const int c = tid + p * 256;
        rowv[p] = c >> 3;            // 8 chunks per 64-half row
        colv[p] = (c & 7) * 8;       // halves offset
    }

    const int a_row = ((lane >> 3) & 1) * 8 + (lane & 7);
    const int a_k   = ((lane >> 4) & 1) * 8;
    const int b_col = ((lane >> 4) & 1) * 8 + (lane & 7);
    const int b_k   = ((lane >> 3) & 1) * 8;

    float acc[4][4][4] = {};

    auto issue = [&](int kblk, int buf) {
        const int kof = kblk * FBK;
        const uint32_t ab = smem_base + (uint32_t)(buf * STG_ELEMS) * 2;
        const uint32_t bb = smem_base + (uint32_t)(b_region + buf * STG_ELEMS) * 2;
#pragma unroll
        for (int p = 0; p < 4; p++) {
            const uint32_t so = (uint32_t)(rowv[p] * LSTR + colv[p]) * 2;
            cp_async16(ab + so, Amat + (size_t)(m0 + rowv[p]) * KIN + kof + colv[p]);
            cp_async16(bb + so, Bmat + (size_t)(n0 + rowv[p]) * KIN + kof + colv[p]);
        }
    };

    // prologue fills stages 0 and 1
#pragma unroll
    for (int s = 0; s < STAGES - 1; s++) { issue(s, s); cp_commit(); }

    int cbuf = 0;             // compute buffer this iteration
    int lbuf = STAGES - 1;    // load target this iteration
    for (int it = 0; it < NIT; it++) {
        cp_wait<STAGES - 2>();           // stage `it` resident
        __syncthreads();                  // all warps done reading lbuf's old data
        {
            const int ldk = it + STAGES - 1;
            if (ldk < NIT) issue(ldk, lbuf);
            cp_commit();
        }
        const uint32_t ab = smem_base + (uint32_t)(cbuf * STG_ELEMS) * 2;
        const uint32_t bb = smem_base + (uint32_t)(b_region + cbuf * STG_ELEMS) * 2;

#pragma unroll
        for (int ks = 0; ks < FBK; ks += 16) {
            uint32_t af[4][4], bf[4][2];
#pragma unroll
            for (int mi = 0; mi < 4; mi++) {
                const int row = wm * 64 + mi * 16 + a_row;
                ldsm_x4(af[mi], ab + (uint32_t)(row * LSTR + ks + a_k) * 2);
            }
#pragma unroll
            for (int p = 0; p < 2; p++) {
                const int col = wn * 32 + p * 16 + b_col;
                uint32_t r4[4];
                ldsm_x4(r4, bb + (uint32_t)(col * LSTR + ks + b_k) * 2);
                bf[2 * p][0] = r4[0]; bf[2 * p][1] = r4[1];
                bf[2 * p + 1][0] = r4[2]; bf[2 * p + 1][1] = r4[3];
            }
#pragma unroll
            for (int mi = 0; mi < 4; mi++)
#pragma unroll
                for (int ni = 0; ni < 4; ni++)
                    mma_f16_k16(acc[mi][ni], af[mi], bf[ni]);
        }
        cbuf = (cbuf + 1 == STAGES) ? 0 : cbuf + 1;
        lbuf = (lbuf + 1 == STAGES) ? 0 : lbuf + 1;
    }

    // ---- fused gate epilogue ----
#pragma unroll
    for (int mi = 0; mi < 4; mi++) {
#pragma unroll
        for (int ni = 0; ni < 4; ni++) {
            const int col   = n0 + wn * 32 + ni * 8 + t4 * 2;
            const int rbase = m0 + wm * 64 + mi * 16 + g;
            const float* c = acc[mi][ni];
#pragma unroll
            for (int half = 0; half < 2; half++) {
                const int row = rbase + half * 8;
                const float v0 = c[half * 2 + 0];
                const float v1 = c[half * 2 + 1];
                const size_t idx = (size_t)row * HDIM + col;
                if (gate == 0) {
                    const float s0 = sigmoidf(v0 + g_az[col]);
                    const float s1 = sigmoidf(v1 + g_az[col + 1]);
                    if (hflag) {
                        float2 o = { s0, s1 };
                        *(float2*)(g_zt + idx) = o;
                    } else {
                        *(__half2*)(g_omz16 + idx) = __floats2half2_rn(1.f - s0, 1.f - s1);
                    }
                } else if (gate == 1) {
                    float2 o = { sigmoidf(v0 + g_ar[col])     * hvec[col],
                                 sigmoidf(v1 + g_ar[col + 1]) * hvec[col + 1] };
                    *(float2*)(g_u + idx) = o;
                } else {
                    const float t0 = v0 + bxh[col];
                    const float t1 = v1 + bxh[col + 1];
                    if (hflag) {
                        float2 o = { t0, t1 };
                        *(float2*)(g_tpre + idx) = o;
                    } else {
                        *(__half2*)(g_th16 + idx) = __floats2half2_rn(tanhf(t0), tanhf(t1));
                    }
                }
            }
        }
    }
}

// ====== tf32 GEMM mainloop (k_gemm_h path; dead when h == 0) =================
__device__ __forceinline__ void gemm_tf32_tile(
    const float* __restrict__ A, const float* __restrict__ Bm,
    int m0, int n0, int KD, float acc[4][4][4])
{
    __shared__ float As[2][BM][TSPAD];
    __shared__ float Bs[2][BN][TSPAD];

    const int tid  = threadIdx.x;
    const int r    = tid >> 1;
    const int cb   = (tid & 1) * 8;
    const int lane = tid & 31;
    const int wid  = tid >> 5;
    const int wm   = wid & 1;
    const int wn   = wid >> 1;
    const int g    = lane >> 2;
    const int t4   = lane & 3;

    const float* ag = A  + (size_t)(m0 + r) * KD + cb;
    const float* bg = Bm + (size_t)(n0 + r) * KD + cb;

    float4 av0 = *(const float4*)(ag);
    float4 av1 = *(const float4*)(ag + 4);
    float4 bv0 = *(const float4*)(bg);
    float4 bv1 = *(const float4*)(bg + 4);
    sts_tf32_8(&As[0][r][cb], av0, av1);
    sts_tf32_8(&Bs[0][r][cb], bv0, bv1);
    __syncthreads();

    int buf = 0;
    for (int k0 = 0; k0 < KD; k0 += TBKH) {
        const bool more = (k0 + TBKH) < KD;
        if (more) {
            av0 = *(const float4*)(ag + k0 + TBKH);
            av1 = *(const float4*)(ag + k0 + TBKH + 4);
            bv0 = *(const float4*)(bg + k0 + TBKH);
            bv1 = *(const float4*)(bg + k0 + TBKH + 4);
        }
#pragma unroll
        for (int kk = 0; kk < TBKH; kk += 8) {
            unsigned afr[4][4], bfr[4][2];
#pragma unroll
            for (int mi = 0; mi < 4; mi++) {
                const int row = wm * 64 + mi * 16 + g;
                afr[mi][0] = __float_as_uint(As[buf][row    ][kk + t4]);
                afr[mi][1] = __float_as_uint(As[buf][row + 8][kk + t4]);
                afr[mi][2] = __float_as_uint(As[buf][row    ][kk + 4 + t4]);
                afr[mi][3] = __float_as_uint(As[buf][row + 8][kk + 4 + t4]);
            }
#pragma unroll
            for (int ni = 0; ni < 4; ni++) {
                const int col = wn * 32 + ni * 8 + g;
                bfr[ni][0] = __float_as_uint(Bs[buf][col][kk + t4]);
                bfr[ni][1] = __float_as_uint(Bs[buf][col][kk + 4 + t4]);
            }
#pragma unroll
            for (int mi = 0; mi < 4; mi++)
#pragma unroll
                for (int ni = 0; ni < 4; ni++)
                    mma_tf32(acc[mi][ni], afr[mi], bfr[ni]);
        }
        if (more) {
            sts_tf32_8(&As[buf ^ 1][r][cb], av0, av1);
            sts_tf32_8(&Bs[buf ^ 1][r][cb], bv0, bv1);
        }
        __syncthreads();
        buf ^= 1;
    }
}

// ------ k_gemm_h: g_tpre += u @ Wh_h^T (only when h != 0) --------------------
__global__ __launch_bounds__(256) void k_gemm_h(const float* __restrict__ Whh) {
    if (g_hflag == 0) return;
    const int m0 = blockIdx.x * BM;
    const int n0 = blockIdx.y * BN;

    float acc[4][4][4] = {};
    gemm_tf32_tile(g_u, Whh, m0, n0, HDIM, acc);

    const int lane = threadIdx.x & 31;
    const int wid  = threadIdx.x >> 5;
    const int wm   = wid & 1;
    const int wn   = wid >> 1;
    const int g    = lane >> 2;
    const int t4   = lane & 3;

#pragma unroll
    for (int mi = 0; mi < 4; mi++) {
#pragma unroll
        for (int ni = 0; ni < 4; ni++) {
            const int col   = n0 + wn * 32 + ni * 8 + t4 * 2;
            const int rbase = m0 + wm * 64 + mi * 16 + g;
            const float* c = acc[mi][ni];
#pragma unroll
            for (int half = 0; half < 2; half++) {
                const int row = rbase + half * 8;
                float* p = g_tpre + (size_t)row * HDIM + col;
                float2 o = *(float2*)p;
                o.x += c[half * 2 + 0];
                o.y += c[half * 2 + 1];
                *(float2*)p = o;
            }
        }
    }
}

// ------ k_final: output head -------------------------------------------------
__global__ __launch_bounds__(256) void k_final(
    const float* __restrict__ h,
    const float* __restrict__ Wy,
    const float* __restrict__ by,
    float* __restrict__ out)
{
    const int tid = threadIdx.x;
    const int hflag = g_hflag;
    const float* wy0 = Wy;
    const float* wy1 = Wy + HDIM;
    __shared__ float s0[256], s1[256];

#pragma unroll
    for (int sub = 0; sub < 2; sub++) {
        const int b = blockIdx.x * 2 + sub;
        float a0 = 0.f, a1 = 0.f;
        if (hflag) {
            for (int j = tid; j < HDIM; j += 256) {
                const size_t idx = (size_t)b * HDIM + j;
                const float z = g_zt[idx];
                const float hn = z * h[j] + (1.f - z) * tanhf(g_tpre[idx]);
                a0 = fmaf(hn, wy0[j], a0);
                a1 = fmaf(hn, wy1[j], a1);
            }
        } else {
            const __half2* om = (const __half2*)(g_omz16 + (size_t)b * HDIM);
            const __half2* th = (const __half2*)(g_th16  + (size_t)b * HDIM);
            for (int j2 = tid; j2 < HDIM / 2; j2 += 256) {
                const float2 o = __half22float2(om[j2]);
                const float2 t = __half22float2(th[j2]);
                const float hn0 = o.x * t.x;
                const float hn1 = o.y * t.y;
                const int j = j2 * 2;
                a0 = fmaf(hn0, wy0[j], fmaf(hn1, wy0[j + 1], a0));
                a1 = fmaf(hn0, wy1[j], fmaf(hn1, wy1[j + 1], a1));
            }
        }
        s0[tid] = a0; s1[tid] = a1;
        __syncthreads();
        for (int off = 128; off > 0; off >>= 1) {
            if (tid < off) { s0[tid] += s0[tid + off]; s1[tid] += s1[tid + off]; }
            __syncthreads();
        }
        if (tid == 0) {
            out[b * OUTN + 0] = s0[0] + by[0];
            out[b * OUTN + 1] = s1[0] + by[1];
        }
        __syncthreads();
    }
}

// ------ launch ---------------------------------------------------------------
extern "C" void kernel_launch(void* const* d_in, const int* in_sizes, int n_in,
                              void* d_out, int out_size) {
    const float* x   = (const float*)d_in[0];
    const float* h   = (const float*)d_in[1];
    const float* Wxz = (const float*)d_in[2];
    const float* bxz = (const float*)d_in[3];
    const float* Wxr = (const float*)d_in[4];
    const float* bxr = (const float*)d_in[5];
    const float* Wxh = (const float*)d_in[6];
    const float* bxh = (const float*)d_in[7];
    const float* Whz = (const float*)d_in[8];
    const float* Whr = (const float*)d_in[9];
    const float* Whh = (const float*)d_in[10];
    const float* Wy  = (const float*)d_in[11];
    const float* by  = (const float*)d_in[12];
    float* out = (float*)d_out;

    static int smem_set = 0;
    if (!smem_set) {
        cudaFuncSetAttribute(k_gemm_in, cudaFuncAttributeMaxDynamicSharedMemorySize,
                             SMEM_BYTES);
        smem_set = 1;
    }

    k_flag<<<1, 256>>>(h);
    k_cvt_all<<<2048, 256>>>(x, Wxz, Wxr, Wxh);
    k_gemv<<<HDIM, 256>>>(h, Whz, Whr, bxz, bxr);

    dim3 g1(BATCH / BM, 3 * (HDIM / BN));
    k_gemm_in<<<g1, 256, SMEM_BYTES>>>(bxh, h);

    dim3 g2(BATCH / BM, HDIM / BN);
    k_gemm_h<<<g2, 256>>>(Whh);

    k_final<<<BATCH / 2, 256>>>(h, Wy, by, out);
}